// round 6
// baseline (speedup 1.0000x reference)
#include <cuda_runtime.h>
#include <cuda_bf16.h>
#include <cstdint>

// ---------------- problem constants ----------------
#define BATCH    4096
#define N_COL    100
#define N_COND   64
#define TOTAL    6400
#define N_RODT   1600
#define N_EST    160
#define N_FOREST 100
#define N_HID    128
#define N_CLASS  10
#define EPSV     1e-5f
#define SDIM     136      // smem row stride (floats); conflict-free fragment access

// ---------------- device scratch ----------------
__device__ float  g_xT [N_COL * BATCH];
__device__ float  g_wT [N_RODT * BATCH];
__device__ float  g_Etf[N_RODT * N_HID];                      // tf32(E)
__device__ float  g_W1p[N_HID * N_HID];                       // tf32(fc1w * ln1w) [d][o]
__device__ float4 g_W1frag[4096];                             // W1p in mma-fragment order
__device__ float  g_wc2[N_HID * 12];                          // tf32(fc2w * ln2w) [o][12]
__device__ float  g_s1[N_HID], g_d1[N_HID];
__device__ float  g_s2[16],    g_d2[16];
__device__ float  g_Y  [(size_t)N_FOREST * BATCH * N_CLASS];

__device__ __forceinline__ float to_tf32(float x) {
    uint32_t u;
    asm("cvt.rna.tf32.f32 %0, %1;" : "=r"(u) : "f"(x));
    return __uint_as_float(u);
}
__device__ __forceinline__ void cpasync16(uint32_t dst, const void* src) {
    asm volatile("cp.async.cg.shared.global [%0], [%1], 16;" :: "r"(dst), "l"(src));
}
#define CP_COMMIT asm volatile("cp.async.commit_group;")
#define CP_WAIT0  asm volatile("cp.async.wait_group 0;")

// =====================================================================
// Kernel 0: transpose x
// =====================================================================
__global__ void k0_transpose(const float* __restrict__ x) {
    int i = blockIdx.x * 256 + threadIdx.x;
    int c = i >> 12;
    int b = i & 4095;
    g_xT[i] = x[b * N_COL + c];
}

// =====================================================================
// k_pre: tf32-round E; W1' = fc1w*ln1w; wc2 = fc2w*ln2w
// =====================================================================
__global__ void k_pre(const float* __restrict__ E, const float* __restrict__ fc1w,
                      const float* __restrict__ ln1w, const float* __restrict__ fc2w,
                      const float* __restrict__ ln2w) {
    int i = blockIdx.x * 256 + threadIdx.x;
    if (i < N_RODT * N_HID) g_Etf[i] = to_tf32(E[i]);
    if (i < N_HID * N_HID) {
        int d = i >> 7;
        g_W1p[i] = to_tf32(fc1w[i] * ln1w[d]);
    }
    if (i < N_HID * 12) {
        int o = i / 12, c = i % 12;
        g_wc2[i] = (c < 10) ? to_tf32(fc2w[o * 10 + c] * ln2w[o]) : 0.f;
    }
}
__global__ void k_pre2(const float* __restrict__ fc1w, const float* __restrict__ fc1b,
                       const float* __restrict__ ln1b, const float* __restrict__ fc2w,
                       const float* __restrict__ fc2b, const float* __restrict__ ln2b) {
    int o = threadIdx.x;
    float s = 0.f, d = 0.f;
    for (int k = 0; k < 128; k++) {
        s += g_W1p[k * 128 + o];
        d += fc1w[k * 128 + o] * ln1b[k];
    }
    g_s1[o] = s;
    g_d1[o] = d + fc1b[o];
    if (o < 10) {
        float s2 = 0.f, d2 = 0.f;
        for (int k = 0; k < 128; k++) {
            s2 += g_wc2[k * 12 + o];
            d2 += ln2b[k] * fc2w[k * 10 + o];
        }
        g_s2[o] = s2;
        g_d2[o] = d2 + fc2b[o];
    } else if (o < 16) {
        g_s2[o] = 0.f; g_d2[o] = 0.f;
    }
}
// build fragment-ordered W1: idx = ks*256 + wm*64 + h*32 + t*8 + g
// value float4 = W1p[(8ks+t+4h)][wm*32+g + {0,8,16,24}]
__global__ void k_pre3() {
    int i = blockIdx.x * 256 + threadIdx.x;   // 4096
    int g  = i & 7;
    int t  = (i >> 3) & 3;
    int h  = (i >> 5) & 1;
    int wm = (i >> 6) & 3;
    int ks = i >> 8;
    int k  = 8 * ks + t + 4 * h;
    int m  = wm * 32 + g;
    float4 v;
    v.x = g_W1p[k * 128 + m];
    v.y = g_W1p[k * 128 + m + 8];
    v.z = g_W1p[k * 128 + m + 16];
    v.w = g_W1p[k * 128 + m + 24];
    g_W1frag[i] = v;
}

// =====================================================================
// Kernel 1: condition gen + rODT scoring — 4 b's per thread
// =====================================================================
__global__ void k1_rodt(const float* __restrict__ w1, const float* __restrict__ b1,
                        const int*   __restrict__ perm,
                        const float* __restrict__ gn1w, const float* __restrict__ gn1b,
                        const float* __restrict__ c2w,  const float* __restrict__ c2b,
                        const float* __restrict__ gn2w, const float* __restrict__ gn2b,
                        const float* __restrict__ c3w,  const float* __restrict__ c3b) {
    int g   = blockIdx.x;
    int tid = threadIdx.x;
    __shared__ int   sc[4];
    __shared__ float sw1[4], sb1[4], sg1w[4], sg1b[4];
    __shared__ float sw2[16], sb2[4], sg2w[4], sg2b[4], sw3[4], sb3;
    if (tid < 4) {
        int t = 4 * g + tid;
        int p = perm[t];
        int c = p % N_COL;
        int j = p / N_COL;
        sc [tid] = c;
        sw1[tid] = w1[c * N_COND + j];
        sb1[tid] = b1[c * N_COND + j];
        sg1w[tid] = gn1w[t];  sg1b[tid] = gn1b[t];
        sb2 [tid] = c2b[t];
        sg2w[tid] = gn2w[t];  sg2b[tid] = gn2b[t];
        sw3 [tid] = c3w[g * 4 + tid];
    }
    if (tid < 16) sw2[tid] = c2w[g * 16 + tid];
    if (tid == 31) sb3 = c3b[g];
    __syncthreads();

    const int b = blockIdx.y * 1024 + tid * 4;
    float4 xv[4];
#pragma unroll
    for (int k = 0; k < 4; k++)
        xv[k] = *(const float4*)&g_xT[sc[k] * BATCH + b];

    float out[4];
#pragma unroll
    for (int j = 0; j < 4; j++) {
        float v[4];
#pragma unroll
        for (int k = 0; k < 4; k++) {
            float xval = (&xv[k].x)[j];
            float z = fmaf(xval, sw1[k], sb1[k]);
            v[k] = 1.f / (1.f + __expf(-z));
        }
        float mu = 0.25f * (v[0] + v[1] + v[2] + v[3]);
        float var = 0.f;
#pragma unroll
        for (int k = 0; k < 4; k++) { float d = v[k] - mu; var += d * d; }
        var *= 0.25f;
        float rs = rsqrtf(var + EPSV);
        float n[4];
#pragma unroll
        for (int k = 0; k < 4; k++) n[k] = fmaf((v[k] - mu) * rs, sg1w[k], sg1b[k]);
        float h[4];
#pragma unroll
        for (int o = 0; o < 4; o++) {
            float a = sb2[o];
#pragma unroll
            for (int k = 0; k < 4; k++) a = fmaf(n[k], sw2[k * 4 + o], a);
            h[o] = fmaxf(a, 0.f);
        }
        float mu2 = 0.25f * (h[0] + h[1] + h[2] + h[3]);
        float var2 = 0.f;
#pragma unroll
        for (int k = 0; k < 4; k++) { float d = h[k] - mu2; var2 += d * d; }
        var2 *= 0.25f;
        float rs2 = rsqrtf(var2 + EPSV);
        float wo = sb3;
#pragma unroll
        for (int k = 0; k < 4; k++)
            wo = fmaf(fmaf((h[k] - mu2) * rs2, sg2w[k], sg2b[k]), sw3[k], wo);
        out[j] = wo;
    }
    *(float4*)&g_wT[(size_t)g * BATCH + b] = make_float4(out[0], out[1], out[2], out[3]);
}

// =====================================================================
// tf32 m16n8k8 mma
// =====================================================================
__device__ __forceinline__ void mma_tf32(float* c, const uint32_t* a, const uint32_t* b) {
    asm volatile("mma.sync.aligned.m16n8k8.row.col.f32.tf32.tf32.f32 "
                 "{%0,%1,%2,%3}, {%4,%5,%6,%7}, {%8,%9}, {%0,%1,%2,%3};"
                 : "+f"(c[0]), "+f"(c[1]), "+f"(c[2]), "+f"(c[3])
                 : "r"(a[0]), "r"(a[1]), "r"(a[2]), "r"(a[3]), "r"(b[0]), "r"(b[1]));
}

// smem-smem GEMM used for GEMM A (E in smem). 16 warps, 32x32 warp tiles.
template<int KSTEPS>
__device__ __forceinline__ void gemm512(const float* __restrict__ Asm,
                                        const float* __restrict__ Bsm,
                                        int warp, int lane, float acc[2][4][4]) {
    const int M0 = (warp & 3) * 32, N0 = (warp >> 2) * 32;
    const int g = lane >> 2, t = lane & 3;
#pragma unroll
    for (int ks = 0; ks < KSTEPS; ks++) {
        const int k0 = ks * 8;
        const float* ab = Asm + (k0 + t) * SDIM + M0 + g;
        uint32_t a[2][4];
        a[0][0] = __float_as_uint(ab[0]);
        a[0][1] = __float_as_uint(ab[8]);
        a[0][2] = __float_as_uint(ab[4 * SDIM]);
        a[0][3] = __float_as_uint(ab[4 * SDIM + 8]);
        a[1][0] = __float_as_uint(ab[16]);
        a[1][1] = __float_as_uint(ab[24]);
        a[1][2] = __float_as_uint(ab[4 * SDIM + 16]);
        a[1][3] = __float_as_uint(ab[4 * SDIM + 24]);
        const float* bb = Bsm + (k0 + t) * SDIM + N0 + g;
        uint32_t bf[4][2];
#pragma unroll
        for (int nt = 0; nt < 4; nt++) {
            bf[nt][0] = __float_as_uint(bb[nt * 8]);
            bf[nt][1] = __float_as_uint(bb[nt * 8 + 4 * SDIM]);
        }
#pragma unroll
        for (int mt = 0; mt < 2; mt++)
#pragma unroll
            for (int nt = 0; nt < 4; nt++) mma_tf32(acc[mt][nt], a[mt], bf[nt]);
    }
}

// =====================================================================
// k23: fused forest GEMM + MLP (LN folded). GEMM B loads W1 fragments via LDG.
// dynamic smem: Pf[160][136] (P -> C~ -> H), Wb0[80][136], Wb1[80][136]
// =====================================================================
#define K23_SMEM ((160 * SDIM + 80 * SDIM + 80 * SDIM) * 4)   // 174080
__global__ void __launch_bounds__(512, 1) k23_forest_mlp(const int* __restrict__ swr) {
    extern __shared__ char sh[];
    float* Pf  = (float*)sh;
    float* Wb0 = (float*)(sh + 160 * SDIM * 4);
    float* Wb1 = (float*)(sh + (160 + 80) * SDIM * 4);

    __shared__ int   s_idx[160];
    __shared__ float s_invS[128];
    __shared__ float s_redA[512], s_redB[512];
    __shared__ float s_mu[128], s_rs[128];
    __shared__ float s_s1[128], s_d1[128];
    __shared__ __align__(16) float s_wc2[128 * 12];
    __shared__ float s_s2[16], s_d2[16];

    const int tid = threadIdx.x, lane = tid & 31, warp = tid >> 5;
    const int f = blockIdx.y;
    const int b0 = blockIdx.x * 128;

    if (tid < 160) s_idx[tid] = swr[f * N_EST + tid];
    __syncthreads();

    // ---- E half0 via cp.async ----
    {
        uint32_t wb0 = (uint32_t)__cvta_generic_to_shared(Wb0);
#pragma unroll
        for (int i = tid; i < 80 * 32; i += 512) {
            int e = i >> 5, q = i & 31;
            cpasync16(wb0 + (e * SDIM + q * 4) * 4, g_Etf + (size_t)s_idx[e] * N_HID + q * 4);
        }
        CP_COMMIT;
    }

    // ---- stage P = tf32(exp(w)); params ----
#pragma unroll
    for (int i = tid; i < 160 * 32; i += 512) {
        int e = i >> 5, b4 = i & 31;
        float4 v = *(const float4*)(g_wT + (size_t)s_idx[e] * BATCH + b0 + b4 * 4);
        float* dst = Pf + e * SDIM + b4 * 4;
        dst[0] = to_tf32(__expf(v.x));
        dst[1] = to_tf32(__expf(v.y));
        dst[2] = to_tf32(__expf(v.z));
        dst[3] = to_tf32(__expf(v.w));
    }
    if (tid < 128) { s_s1[tid] = g_s1[tid]; s_d1[tid] = g_d1[tid]; }
    for (int i = tid; i < 1536; i += 512) s_wc2[i] = g_wc2[i];
    if (tid < 16) { s_s2[tid] = g_s2[tid]; s_d2[tid] = g_d2[tid]; }
    CP_WAIT0;
    __syncthreads();

    // ---- E half1 -> Wb1 ----
    {
        uint32_t wb1 = (uint32_t)__cvta_generic_to_shared(Wb1);
#pragma unroll
        for (int i = tid; i < 80 * 32; i += 512) {
            int e = i >> 5, q = i & 31;
            cpasync16(wb1 + (e * SDIM + q * 4) * 4, g_Etf + (size_t)s_idx[80 + e] * N_HID + q * 4);
        }
        CP_COMMIT;
    }

    // ---- invS: column sums of P ----
    {
        const int col = tid & 127, q = tid >> 7;
        float s = 0.f;
        for (int r = 0; r < 40; r++) s += Pf[(q * 40 + r) * SDIM + col];
        s_redA[q * 128 + col] = s;
    }
    __syncthreads();
    if (tid < 128)
        s_invS[tid] = 1.f / (s_redA[tid] + s_redA[128 + tid] + s_redA[256 + tid] + s_redA[384 + tid]);

    // ---- GEMM A (K=160, two halves) ----
    float acc[2][4][4];
#pragma unroll
    for (int mt = 0; mt < 2; mt++)
#pragma unroll
        for (int nt = 0; nt < 4; nt++)
#pragma unroll
            for (int r = 0; r < 4; r++) acc[mt][nt][r] = 0.f;
    gemm512<10>(Wb0, Pf, warp, lane, acc);
    CP_WAIT0;
    __syncthreads();
    gemm512<10>(Wb1, Pf + 80 * SDIM, warp, lane, acc);
    __syncthreads();   // all P reads done before overwrite

    // epilogue A: C~ = tf32(acc * invS) -> Pf rows 0..127
    {
        const int M0 = (warp & 3) * 32, N0 = (warp >> 2) * 32;
        const int g = lane >> 2, q2 = (lane & 3) * 2;
#pragma unroll
        for (int mt = 0; mt < 2; mt++)
#pragma unroll
            for (int nt = 0; nt < 4; nt++) {
                int row = M0 + mt * 16 + g, col = N0 + nt * 8 + q2;
                float i0 = s_invS[col], i1 = s_invS[col + 1];
                Pf[row * SDIM + col]           = to_tf32(acc[mt][nt][0] * i0);
                Pf[row * SDIM + col + 1]       = to_tf32(acc[mt][nt][1] * i1);
                Pf[(row + 8) * SDIM + col]     = to_tf32(acc[mt][nt][2] * i0);
                Pf[(row + 8) * SDIM + col + 1] = to_tf32(acc[mt][nt][3] * i1);
            }
    }
    __syncthreads();

    // ---- stats1 ----
    {
        const int col = tid & 127, q = tid >> 7;
        float s = 0.f, s2 = 0.f;
        for (int r = 0; r < 32; r++) {
            float v = Pf[(q * 32 + r) * SDIM + col];
            s += v; s2 += v * v;
        }
        s_redA[q * 128 + col] = s;
        s_redB[q * 128 + col] = s2;
    }
    __syncthreads();
    if (tid < 128) {
        float s  = s_redA[tid] + s_redA[128 + tid] + s_redA[256 + tid] + s_redA[384 + tid];
        float s2 = s_redB[tid] + s_redB[128 + tid] + s_redB[256 + tid] + s_redB[384 + tid];
        float mu = s * (1.f / 128.f);
        float var = fmaxf(s2 * (1.f / 128.f) - mu * mu, 0.f);
        s_mu[tid] = mu;
        s_rs[tid] = rsqrtf(var + EPSV);
    }
    __syncthreads();

    // ---- GEMM B: W1 fragments via LDG from g_W1frag, C~ from Pf ----
#pragma unroll
    for (int mt = 0; mt < 2; mt++)
#pragma unroll
        for (int nt = 0; nt < 4; nt++)
#pragma unroll
            for (int r = 0; r < 4; r++) acc[mt][nt][r] = 0.f;
    {
        const int wm = warp & 3, N0 = (warp >> 2) * 32;
        const int g = lane >> 2, t = lane & 3;
        const float4* wfb = g_W1frag + wm * 64 + t * 8 + g;
#pragma unroll
        for (int ks = 0; ks < 16; ks++) {
            float4 f0 = wfb[ks * 256];
            float4 f1 = wfb[ks * 256 + 32];
            uint32_t a[2][4];
            a[0][0] = __float_as_uint(f0.x);
            a[0][1] = __float_as_uint(f0.y);
            a[0][2] = __float_as_uint(f1.x);
            a[0][3] = __float_as_uint(f1.y);
            a[1][0] = __float_as_uint(f0.z);
            a[1][1] = __float_as_uint(f0.w);
            a[1][2] = __float_as_uint(f1.z);
            a[1][3] = __float_as_uint(f1.w);
            const float* bb = Pf + (ks * 8 + t) * SDIM + N0 + g;
            uint32_t bf[4][2];
#pragma unroll
            for (int nt = 0; nt < 4; nt++) {
                bf[nt][0] = __float_as_uint(bb[nt * 8]);
                bf[nt][1] = __float_as_uint(bb[nt * 8 + 4 * SDIM]);
            }
#pragma unroll
            for (int mt = 0; mt < 2; mt++)
#pragma unroll
                for (int nt = 0; nt < 4; nt++) mma_tf32(acc[mt][nt], a[mt], bf[nt]);
        }
    }
    __syncthreads();   // all C~ reads done before overwrite

    // epilogue B: H = relu(rs*(G - mu*s1) + d1) -> Pf rows 0..127
    {
        const int M0 = (warp & 3) * 32, N0 = (warp >> 2) * 32;
        const int g = lane >> 2, q2 = (lane & 3) * 2;
#pragma unroll
        for (int mt = 0; mt < 2; mt++)
#pragma unroll
            for (int nt = 0; nt < 4; nt++) {
                int row = M0 + mt * 16 + g, col = N0 + nt * 8 + q2;
                float s1a = s_s1[row], d1a = s_d1[row];
                float s1b = s_s1[row + 8], d1b = s_d1[row + 8];
                float mu0 = s_mu[col], rs0 = s_rs[col];
                float mu1 = s_mu[col + 1], rs1 = s_rs[col + 1];
                Pf[row * SDIM + col]           = fmaxf(fmaf(rs0, acc[mt][nt][0] - mu0 * s1a, d1a), 0.f);
                Pf[row * SDIM + col + 1]       = fmaxf(fmaf(rs1, acc[mt][nt][1] - mu1 * s1a, d1a), 0.f);
                Pf[(row + 8) * SDIM + col]     = fmaxf(fmaf(rs0, acc[mt][nt][2] - mu0 * s1b, d1b), 0.f);
                Pf[(row + 8) * SDIM + col + 1] = fmaxf(fmaf(rs1, acc[mt][nt][3] - mu1 * s1b, d1b), 0.f);
            }
    }
    __syncthreads();

    // ---- stats2 ----
    {
        const int col = tid & 127, q = tid >> 7;
        float s = 0.f, s2 = 0.f;
        for (int r = 0; r < 32; r++) {
            float v = Pf[(q * 32 + r) * SDIM + col];
            s += v; s2 += v * v;
        }
        s_redA[q * 128 + col] = s;
        s_redB[q * 128 + col] = s2;
    }
    __syncthreads();
    if (tid < 128) {
        float s  = s_redA[tid] + s_redA[128 + tid] + s_redA[256 + tid] + s_redA[384 + tid];
        float s2 = s_redB[tid] + s_redB[128 + tid] + s_redB[256 + tid] + s_redB[384 + tid];
        float mu = s * (1.f / 128.f);
        float var = fmaxf(s2 * (1.f / 128.f) - mu * mu, 0.f);
        s_mu[tid] = mu;
        s_rs[tid] = rsqrtf(var + EPSV);
    }
    __syncthreads();

    // ---- fc2 (LN2 folded) ----
    {
        const int b = tid >> 2, q = tid & 3;
        float a10[10];
#pragma unroll
        for (int c = 0; c < 10; c++) a10[c] = 0.f;
#pragma unroll 4
        for (int i = 0; i < 32; i++) {
            int o = 4 * i + q;
            float h = Pf[o * SDIM + b];
            const float* wr = s_wc2 + o * 12;
            float4 w0 = *(const float4*)wr;
            float4 w1 = *(const float4*)(wr + 4);
            float2 w2 = *(const float2*)(wr + 8);
            a10[0] = fmaf(h, w0.x, a10[0]);
            a10[1] = fmaf(h, w0.y, a10[1]);
            a10[2] = fmaf(h, w0.z, a10[2]);
            a10[3] = fmaf(h, w0.w, a10[3]);
            a10[4] = fmaf(h, w1.x, a10[4]);
            a10[5] = fmaf(h, w1.y, a10[5]);
            a10[6] = fmaf(h, w1.z, a10[6]);
            a10[7] = fmaf(h, w1.w, a10[7]);
            a10[8] = fmaf(h, w2.x, a10[8]);
            a10[9] = fmaf(h, w2.y, a10[9]);
        }
#pragma unroll
        for (int c = 0; c < 10; c++) {
            a10[c] += __shfl_xor_sync(0xffffffff, a10[c], 1);
            a10[c] += __shfl_xor_sync(0xffffffff, a10[c], 2);
        }
        if (q < 2) {
            const int c0 = q * 5;
            float mu2 = s_mu[b], rs2 = s_rs[b];
            size_t R = ((size_t)f * BATCH + b0 + b) * N_CLASS;
#pragma unroll
            for (int j = 0; j < 5; j++) {
                int c = c0 + j;
                g_Y[R + c] = fmaf(rs2, a10[c] - mu2 * s_s2[c], s_d2[c]);
            }
        }
    }
}

// =====================================================================
// k4: mean over forests (float4)
// =====================================================================
__global__ void k4_reduce(float* __restrict__ out) {
    int i = blockIdx.x * 256 + threadIdx.x;   // float4 index
    if (i < BATCH * N_CLASS / 4) {
        float4 s = make_float4(0.f, 0.f, 0.f, 0.f);
        for (int f = 0; f < N_FOREST; f++) {
            float4 v = *((const float4*)(g_Y + (size_t)f * (BATCH * N_CLASS)) + i);
            s.x += v.x; s.y += v.y; s.z += v.z; s.w += v.w;
        }
        out[i * 4 + 0] = s.x * (1.f / N_FOREST);
        out[i * 4 + 1] = s.y * (1.f / N_FOREST);
        out[i * 4 + 2] = s.z * (1.f / N_FOREST);
        out[i * 4 + 3] = s.w * (1.f / N_FOREST);
    }
}

// =====================================================================
extern "C" void kernel_launch(void* const* d_in, const int* in_sizes, int n_in,
                              void* d_out, int out_size) {
    const float* x     = (const float*)d_in[0];
    const float* w1    = (const float*)d_in[1];
    const float* b1    = (const float*)d_in[2];
    const int*   perm  = (const int*)  d_in[3];
    const float* gn1w  = (const float*)d_in[4];
    const float* gn1b  = (const float*)d_in[5];
    const float* c2w   = (const float*)d_in[6];
    const float* c2b   = (const float*)d_in[7];
    const float* gn2w  = (const float*)d_in[8];
    const float* gn2b  = (const float*)d_in[9];
    const float* c3w   = (const float*)d_in[10];
    const float* c3b   = (const float*)d_in[11];
    const int*   swr   = (const int*)  d_in[12];
    const float* E     = (const float*)d_in[13];
    const float* ln1w  = (const float*)d_in[14];
    const float* ln1b  = (const float*)d_in[15];
    const float* fc1w  = (const float*)d_in[16];
    const float* fc1b  = (const float*)d_in[17];
    const float* ln2w  = (const float*)d_in[18];
    const float* ln2b  = (const float*)d_in[19];
    const float* fc2w  = (const float*)d_in[20];
    const float* fc2b  = (const float*)d_in[21];
    float* out = (float*)d_out;

    cudaFuncSetAttribute(k23_forest_mlp, cudaFuncAttributeMaxDynamicSharedMemorySize, K23_SMEM);

    k0_transpose<<<(N_COL * BATCH) / 256, 256>>>(x);
    k_pre<<<(N_RODT * N_HID + 255) / 256, 256>>>(E, fc1w, ln1w, fc2w, ln2w);
    k_pre2<<<1, 128>>>(fc1w, fc1b, ln1b, fc2w, fc2b, ln2b);
    k_pre3<<<16, 256>>>();
    k1_rodt<<<dim3(N_RODT, BATCH / 1024), 256>>>(w1, b1, perm, gn1w, gn1b,
                                                 c2w, c2b, gn2w, gn2b, c3w, c3b);
    k23_forest_mlp<<<dim3(BATCH / 128, N_FOREST), 512, K23_SMEM>>>(swr);
    k4_reduce<<<(BATCH * N_CLASS / 4 + 255) / 256, 256>>>(out);
}

// round 7
// speedup vs baseline: 1.1475x; 1.1475x over previous
#include <cuda_runtime.h>
#include <cuda_bf16.h>
#include <cstdint>

// ---------------- problem constants ----------------
#define BATCH    4096
#define N_COL    100
#define N_COND   64
#define TOTAL    6400
#define N_RODT   1600
#define N_EST    160
#define N_FOREST 100
#define N_HID    128
#define N_CLASS  10
#define EPSV     1e-5f
#define SDIM     136      // smem row stride (floats); conflict-free fragment access

// ---------------- device scratch ----------------
__device__ float g_xT [N_COL * BATCH];
__device__ float g_wT [N_RODT * BATCH];
__device__ float g_Etf[N_RODT * N_HID];                      // tf32(E)
__device__ float g_W1p[N_HID * N_HID];                       // tf32(fc1w * ln1w) [d][o]
__device__ float g_wc2[N_HID * 12];                          // tf32(fc2w * ln2w) [o][12]
__device__ float g_s1[N_HID], g_d1[N_HID];
__device__ float g_s2[16],    g_d2[16];
__device__ float g_Y  [(size_t)N_FOREST * BATCH * N_CLASS];

__device__ __forceinline__ float to_tf32(float x) {
    uint32_t u;
    asm("cvt.rna.tf32.f32 %0, %1;" : "=r"(u) : "f"(x));
    return __uint_as_float(u);
}
__device__ __forceinline__ void cpasync16(uint32_t dst, const void* src) {
    asm volatile("cp.async.cg.shared.global [%0], [%1], 16;" :: "r"(dst), "l"(src));
}
#define CP_COMMIT asm volatile("cp.async.commit_group;")
#define CP_WAIT0  asm volatile("cp.async.wait_group 0;")

// =====================================================================
// Kernel 0: transpose x
// =====================================================================
__global__ void k0_transpose(const float* __restrict__ x) {
    int i = blockIdx.x * 256 + threadIdx.x;
    int c = i >> 12;
    int b = i & 4095;
    g_xT[i] = x[b * N_COL + c];
}

// =====================================================================
// k_pre: tf32-round E; W1' = fc1w*ln1w; wc2 = fc2w*ln2w
// =====================================================================
__global__ void k_pre(const float* __restrict__ E, const float* __restrict__ fc1w,
                      const float* __restrict__ ln1w, const float* __restrict__ fc2w,
                      const float* __restrict__ ln2w) {
    int i = blockIdx.x * 256 + threadIdx.x;
    if (i < N_RODT * N_HID) g_Etf[i] = to_tf32(E[i]);
    if (i < N_HID * N_HID) {
        int d = i >> 7;
        g_W1p[i] = to_tf32(fc1w[i] * ln1w[d]);
    }
    if (i < N_HID * 12) {
        int o = i / 12, c = i % 12;
        g_wc2[i] = (c < 10) ? to_tf32(fc2w[o * 10 + c] * ln2w[o]) : 0.f;
    }
}
__global__ void k_pre2(const float* __restrict__ fc1w, const float* __restrict__ fc1b,
                       const float* __restrict__ ln1b, const float* __restrict__ fc2w,
                       const float* __restrict__ fc2b, const float* __restrict__ ln2b) {
    int o = threadIdx.x;
    float s = 0.f, d = 0.f;
    for (int k = 0; k < 128; k++) {
        s += g_W1p[k * 128 + o];
        d += fc1w[k * 128 + o] * ln1b[k];
    }
    g_s1[o] = s;
    g_d1[o] = d + fc1b[o];
    if (o < 10) {
        float s2 = 0.f, d2 = 0.f;
        for (int k = 0; k < 128; k++) {
            s2 += g_wc2[k * 12 + o];
            d2 += ln2b[k] * fc2w[k * 10 + o];
        }
        g_s2[o] = s2;
        g_d2[o] = d2 + fc2b[o];
    } else if (o < 16) {
        g_s2[o] = 0.f; g_d2[o] = 0.f;
    }
}

// =====================================================================
// Kernel 1: condition gen + rODT scoring — 4 b's per thread
// =====================================================================
__global__ void k1_rodt(const float* __restrict__ w1, const float* __restrict__ b1,
                        const int*   __restrict__ perm,
                        const float* __restrict__ gn1w, const float* __restrict__ gn1b,
                        const float* __restrict__ c2w,  const float* __restrict__ c2b,
                        const float* __restrict__ gn2w, const float* __restrict__ gn2b,
                        const float* __restrict__ c3w,  const float* __restrict__ c3b) {
    int g   = blockIdx.x;
    int tid = threadIdx.x;
    __shared__ int   sc[4];
    __shared__ float sw1[4], sb1[4], sg1w[4], sg1b[4];
    __shared__ float sw2[16], sb2[4], sg2w[4], sg2b[4], sw3[4], sb3;
    if (tid < 4) {
        int t = 4 * g + tid;
        int p = perm[t];
        int c = p % N_COL;
        int j = p / N_COL;
        sc [tid] = c;
        sw1[tid] = w1[c * N_COND + j];
        sb1[tid] = b1[c * N_COND + j];
        sg1w[tid] = gn1w[t];  sg1b[tid] = gn1b[t];
        sb2 [tid] = c2b[t];
        sg2w[tid] = gn2w[t];  sg2b[tid] = gn2b[t];
        sw3 [tid] = c3w[g * 4 + tid];
    }
    if (tid < 16) sw2[tid] = c2w[g * 16 + tid];
    if (tid == 31) sb3 = c3b[g];
    __syncthreads();

    const int b = blockIdx.y * 1024 + tid * 4;
    float4 xv[4];
#pragma unroll
    for (int k = 0; k < 4; k++)
        xv[k] = *(const float4*)&g_xT[sc[k] * BATCH + b];

    float out[4];
#pragma unroll
    for (int j = 0; j < 4; j++) {
        float v[4];
#pragma unroll
        for (int k = 0; k < 4; k++) {
            float xval = (&xv[k].x)[j];
            float z = fmaf(xval, sw1[k], sb1[k]);
            v[k] = 1.f / (1.f + __expf(-z));
        }
        float mu = 0.25f * (v[0] + v[1] + v[2] + v[3]);
        float var = 0.f;
#pragma unroll
        for (int k = 0; k < 4; k++) { float d = v[k] - mu; var += d * d; }
        var *= 0.25f;
        float rs = rsqrtf(var + EPSV);
        float n[4];
#pragma unroll
        for (int k = 0; k < 4; k++) n[k] = fmaf((v[k] - mu) * rs, sg1w[k], sg1b[k]);
        float h[4];
#pragma unroll
        for (int o = 0; o < 4; o++) {
            float a = sb2[o];
#pragma unroll
            for (int k = 0; k < 4; k++) a = fmaf(n[k], sw2[k * 4 + o], a);
            h[o] = fmaxf(a, 0.f);
        }
        float mu2 = 0.25f * (h[0] + h[1] + h[2] + h[3]);
        float var2 = 0.f;
#pragma unroll
        for (int k = 0; k < 4; k++) { float d = h[k] - mu2; var2 += d * d; }
        var2 *= 0.25f;
        float rs2 = rsqrtf(var2 + EPSV);
        float wo = sb3;
#pragma unroll
        for (int k = 0; k < 4; k++)
            wo = fmaf(fmaf((h[k] - mu2) * rs2, sg2w[k], sg2b[k]), sw3[k], wo);
        out[j] = wo;
    }
    *(float4*)&g_wT[(size_t)g * BATCH + b] = make_float4(out[0], out[1], out[2], out[3]);
}

// =====================================================================
// tf32 m16n8k8 mma
// =====================================================================
__device__ __forceinline__ void mma_tf32(float* c, const uint32_t* a, const uint32_t* b) {
    asm volatile("mma.sync.aligned.m16n8k8.row.col.f32.tf32.tf32.f32 "
                 "{%0,%1,%2,%3}, {%4,%5,%6,%7}, {%8,%9}, {%0,%1,%2,%3};"
                 : "+f"(c[0]), "+f"(c[1]), "+f"(c[2]), "+f"(c[3])
                 : "r"(a[0]), "r"(a[1]), "r"(a[2]), "r"(a[3]), "r"(b[0]), "r"(b[1]));
}

// 16 warps, 32x32 warp tiles over 128x128. Asm/Bsm k-major, stride SDIM.
template<int KSTEPS>
__device__ __forceinline__ void gemm512(const float* __restrict__ Asm,
                                        const float* __restrict__ Bsm,
                                        int warp, int lane, float acc[2][4][4]) {
    const int M0 = (warp & 3) * 32, N0 = (warp >> 2) * 32;
    const int g = lane >> 2, t = lane & 3;
#pragma unroll
    for (int ks = 0; ks < KSTEPS; ks++) {
        const int k0 = ks * 8;
        const float* ab = Asm + (k0 + t) * SDIM + M0 + g;
        uint32_t a[2][4];
        a[0][0] = __float_as_uint(ab[0]);
        a[0][1] = __float_as_uint(ab[8]);
        a[0][2] = __float_as_uint(ab[4 * SDIM]);
        a[0][3] = __float_as_uint(ab[4 * SDIM + 8]);
        a[1][0] = __float_as_uint(ab[16]);
        a[1][1] = __float_as_uint(ab[24]);
        a[1][2] = __float_as_uint(ab[4 * SDIM + 16]);
        a[1][3] = __float_as_uint(ab[4 * SDIM + 24]);
        const float* bb = Bsm + (k0 + t) * SDIM + N0 + g;
        uint32_t bf[4][2];
#pragma unroll
        for (int nt = 0; nt < 4; nt++) {
            bf[nt][0] = __float_as_uint(bb[nt * 8]);
            bf[nt][1] = __float_as_uint(bb[nt * 8 + 4 * SDIM]);
        }
#pragma unroll
        for (int mt = 0; mt < 2; mt++)
#pragma unroll
            for (int nt = 0; nt < 4; nt++) mma_tf32(acc[mt][nt], a[mt], bf[nt]);
    }
}

// =====================================================================
// k23: fused forest GEMM + MLP (LN folded into GEMM weights). R5 structure.
// dynamic smem: Pf[160][136] (P -> C~ -> H), Wb0[80][136], Wb1[80][136]
// =====================================================================
#define K23_SMEM ((160 * SDIM + 80 * SDIM + 80 * SDIM) * 4)   // 174080
__global__ void __launch_bounds__(512, 1) k23_forest_mlp(const int* __restrict__ swr) {
    extern __shared__ char sh[];
    float* Pf  = (float*)sh;
    float* Wb0 = (float*)(sh + 160 * SDIM * 4);
    float* Wb1 = (float*)(sh + (160 + 80) * SDIM * 4);

    __shared__ int   s_idx[160];
    __shared__ float s_invS[128];
    __shared__ float s_redA[512], s_redB[512];
    __shared__ float s_mu[128], s_rs[128];
    __shared__ float s_s1[128], s_d1[128];
    __shared__ __align__(16) float s_wc2[128 * 12];
    __shared__ float s_s2[16], s_d2[16];

    const int tid = threadIdx.x, lane = tid & 31, warp = tid >> 5;
    const int f = blockIdx.y;
    const int b0 = blockIdx.x * 128;

    if (tid < 160) s_idx[tid] = swr[f * N_EST + tid];
    __syncthreads();

    // ---- issue E half0 via cp.async ----
    {
        uint32_t wb0 = (uint32_t)__cvta_generic_to_shared(Wb0);
#pragma unroll
        for (int i = tid; i < 80 * 32; i += 512) {
            int e = i >> 5, q = i & 31;
            cpasync16(wb0 + (e * SDIM + q * 4) * 4, g_Etf + (size_t)s_idx[e] * N_HID + q * 4);
        }
        CP_COMMIT;
    }

    // ---- stage P = tf32(exp(w)); load params ----
#pragma unroll
    for (int i = tid; i < 160 * 32; i += 512) {
        int e = i >> 5, b4 = i & 31;
        float4 v = *(const float4*)(g_wT + (size_t)s_idx[e] * BATCH + b0 + b4 * 4);
        float* dst = Pf + e * SDIM + b4 * 4;
        dst[0] = to_tf32(__expf(v.x));
        dst[1] = to_tf32(__expf(v.y));
        dst[2] = to_tf32(__expf(v.z));
        dst[3] = to_tf32(__expf(v.w));
    }
    if (tid < 128) { s_s1[tid] = g_s1[tid]; s_d1[tid] = g_d1[tid]; }
    for (int i = tid; i < 1536; i += 512) s_wc2[i] = g_wc2[i];
    if (tid < 16) { s_s2[tid] = g_s2[tid]; s_d2[tid] = g_d2[tid]; }
    CP_WAIT0;
    __syncthreads();

    // ---- issue E half1 -> Wb1 ----
    {
        uint32_t wb1 = (uint32_t)__cvta_generic_to_shared(Wb1);
#pragma unroll
        for (int i = tid; i < 80 * 32; i += 512) {
            int e = i >> 5, q = i & 31;
            cpasync16(wb1 + (e * SDIM + q * 4) * 4, g_Etf + (size_t)s_idx[80 + e] * N_HID + q * 4);
        }
        CP_COMMIT;
    }

    // ---- invS: column sums of P (160 rows) ----
    {
        const int col = tid & 127, q = tid >> 7;
        float s = 0.f;
        for (int r = 0; r < 40; r++) s += Pf[(q * 40 + r) * SDIM + col];
        s_redA[q * 128 + col] = s;
    }
    __syncthreads();
    if (tid < 128)
        s_invS[tid] = 1.f / (s_redA[tid] + s_redA[128 + tid] + s_redA[256 + tid] + s_redA[384 + tid]);

    // ---- GEMM A: C^T[d][b] = sum_e E[e][d] P[e][b], K=160, two halves ----
    float acc[2][4][4];
#pragma unroll
    for (int mt = 0; mt < 2; mt++)
#pragma unroll
        for (int nt = 0; nt < 4; nt++)
#pragma unroll
            for (int r = 0; r < 4; r++) acc[mt][nt][r] = 0.f;
    gemm512<10>(Wb0, Pf, warp, lane, acc);
    CP_WAIT0;
    __syncthreads();
    // prefetch W1' half0 into Wb0 (Wb0 free now)
    {
        uint32_t wb0 = (uint32_t)__cvta_generic_to_shared(Wb0);
#pragma unroll
        for (int i = tid; i < 64 * 32; i += 512) {
            int k = i >> 5, q = i & 31;
            cpasync16(wb0 + (k * SDIM + q * 4) * 4, g_W1p + k * N_HID + q * 4);
        }
        CP_COMMIT;
    }
    gemm512<10>(Wb1, Pf + 80 * SDIM, warp, lane, acc);
    __syncthreads();   // all P reads done before overwrite
    // prefetch W1' half1 into Wb1
    {
        uint32_t wb1 = (uint32_t)__cvta_generic_to_shared(Wb1);
#pragma unroll
        for (int i = tid; i < 64 * 32; i += 512) {
            int k = i >> 5, q = i & 31;
            cpasync16(wb1 + (k * SDIM + q * 4) * 4, g_W1p + (64 + k) * N_HID + q * 4);
        }
        CP_COMMIT;
    }
    // epilogue A: C~ = tf32(acc * invS) -> Pf rows 0..127
    {
        const int M0 = (warp & 3) * 32, N0 = (warp >> 2) * 32;
        const int g = lane >> 2, q2 = (lane & 3) * 2;
#pragma unroll
        for (int mt = 0; mt < 2; mt++)
#pragma unroll
            for (int nt = 0; nt < 4; nt++) {
                int row = M0 + mt * 16 + g, col = N0 + nt * 8 + q2;
                float i0 = s_invS[col], i1 = s_invS[col + 1];
                Pf[row * SDIM + col]           = to_tf32(acc[mt][nt][0] * i0);
                Pf[row * SDIM + col + 1]       = to_tf32(acc[mt][nt][1] * i1);
                Pf[(row + 8) * SDIM + col]     = to_tf32(acc[mt][nt][2] * i0);
                Pf[(row + 8) * SDIM + col + 1] = to_tf32(acc[mt][nt][3] * i1);
            }
    }
    CP_WAIT0;
    __syncthreads();

    // ---- stats1: per-column mean/rstd of C~ ----
    {
        const int col = tid & 127, q = tid >> 7;
        float s = 0.f, s2 = 0.f;
        for (int r = 0; r < 32; r++) {
            float v = Pf[(q * 32 + r) * SDIM + col];
            s += v; s2 += v * v;
        }
        s_redA[q * 128 + col] = s;
        s_redB[q * 128 + col] = s2;
    }
    __syncthreads();
    if (tid < 128) {
        float s  = s_redA[tid] + s_redA[128 + tid] + s_redA[256 + tid] + s_redA[384 + tid];
        float s2 = s_redB[tid] + s_redB[128 + tid] + s_redB[256 + tid] + s_redB[384 + tid];
        float mu = s * (1.f / 128.f);
        float var = fmaxf(s2 * (1.f / 128.f) - mu * mu, 0.f);
        s_mu[tid] = mu;
        s_rs[tid] = rsqrtf(var + EPSV);
    }
    __syncthreads();

    // ---- GEMM B: G[o][b] = sum_d W1'[d][o] C~[d][b], K=128, two halves ----
#pragma unroll
    for (int mt = 0; mt < 2; mt++)
#pragma unroll
        for (int nt = 0; nt < 4; nt++)
#pragma unroll
            for (int r = 0; r < 4; r++) acc[mt][nt][r] = 0.f;
    gemm512<8>(Wb0, Pf, warp, lane, acc);
    __syncthreads();
    gemm512<8>(Wb1, Pf + 64 * SDIM, warp, lane, acc);
    __syncthreads();   // all C~ reads done before overwrite
    // epilogue B: H = relu(rs_b*(G - mu_b*s1[o]) + d1[o]) -> Pf rows 0..127 (fp32)
    {
        const int M0 = (warp & 3) * 32, N0 = (warp >> 2) * 32;
        const int g = lane >> 2, q2 = (lane & 3) * 2;
#pragma unroll
        for (int mt = 0; mt < 2; mt++)
#pragma unroll
            for (int nt = 0; nt < 4; nt++) {
                int row = M0 + mt * 16 + g, col = N0 + nt * 8 + q2;
                float s1a = s_s1[row], d1a = s_d1[row];
                float s1b = s_s1[row + 8], d1b = s_d1[row + 8];
                float mu0 = s_mu[col], rs0 = s_rs[col];
                float mu1 = s_mu[col + 1], rs1 = s_rs[col + 1];
                Pf[row * SDIM + col]           = fmaxf(fmaf(rs0, acc[mt][nt][0] - mu0 * s1a, d1a), 0.f);
                Pf[row * SDIM + col + 1]       = fmaxf(fmaf(rs1, acc[mt][nt][1] - mu1 * s1a, d1a), 0.f);
                Pf[(row + 8) * SDIM + col]     = fmaxf(fmaf(rs0, acc[mt][nt][2] - mu0 * s1b, d1b), 0.f);
                Pf[(row + 8) * SDIM + col + 1] = fmaxf(fmaf(rs1, acc[mt][nt][3] - mu1 * s1b, d1b), 0.f);
            }
    }
    __syncthreads();

    // ---- stats2: per-column mean/rstd of H ----
    {
        const int col = tid & 127, q = tid >> 7;
        float s = 0.f, s2 = 0.f;
        for (int r = 0; r < 32; r++) {
            float v = Pf[(q * 32 + r) * SDIM + col];
            s += v; s2 += v * v;
        }
        s_redA[q * 128 + col] = s;
        s_redB[q * 128 + col] = s2;
    }
    __syncthreads();
    if (tid < 128) {
        float s  = s_redA[tid] + s_redA[128 + tid] + s_redA[256 + tid] + s_redA[384 + tid];
        float s2 = s_redB[tid] + s_redB[128 + tid] + s_redB[256 + tid] + s_redB[384 + tid];
        float mu = s * (1.f / 128.f);
        float var = fmaxf(s2 * (1.f / 128.f) - mu * mu, 0.f);
        s_mu[tid] = mu;
        s_rs[tid] = rsqrtf(var + EPSV);
    }
    __syncthreads();

    // ---- fc2 (fused LN2) ----
    {
        const int b = tid >> 2, q = tid & 3;
        float a10[10];
#pragma unroll
        for (int c = 0; c < 10; c++) a10[c] = 0.f;
#pragma unroll 4
        for (int i = 0; i < 32; i++) {
            int o = 4 * i + q;
            float h = Pf[o * SDIM + b];
            const float* wr = s_wc2 + o * 12;
            float4 w0 = *(const float4*)wr;
            float4 w1 = *(const float4*)(wr + 4);
            float2 w2 = *(const float2*)(wr + 8);
            a10[0] = fmaf(h, w0.x, a10[0]);
            a10[1] = fmaf(h, w0.y, a10[1]);
            a10[2] = fmaf(h, w0.z, a10[2]);
            a10[3] = fmaf(h, w0.w, a10[3]);
            a10[4] = fmaf(h, w1.x, a10[4]);
            a10[5] = fmaf(h, w1.y, a10[5]);
            a10[6] = fmaf(h, w1.z, a10[6]);
            a10[7] = fmaf(h, w1.w, a10[7]);
            a10[8] = fmaf(h, w2.x, a10[8]);
            a10[9] = fmaf(h, w2.y, a10[9]);
        }
#pragma unroll
        for (int c = 0; c < 10; c++) {
            a10[c] += __shfl_xor_sync(0xffffffff, a10[c], 1);
            a10[c] += __shfl_xor_sync(0xffffffff, a10[c], 2);
        }
        if (q < 2) {
            const int c0 = q * 5;
            float mu2 = s_mu[b], rs2 = s_rs[b];
            size_t R = ((size_t)f * BATCH + b0 + b) * N_CLASS;
#pragma unroll
            for (int j = 0; j < 5; j++) {
                int c = c0 + j;
                g_Y[R + c] = fmaf(rs2, a10[c] - mu2 * s_s2[c], s_d2[c]);
            }
        }
    }
}

// =====================================================================
// k4: mean over forests (float4)
// =====================================================================
__global__ void k4_reduce(float* __restrict__ out) {
    int i = blockIdx.x * 256 + threadIdx.x;   // float4 index
    if (i < BATCH * N_CLASS / 4) {
        float4 s = make_float4(0.f, 0.f, 0.f, 0.f);
        for (int f = 0; f < N_FOREST; f++) {
            float4 v = *((const float4*)(g_Y + (size_t)f * (BATCH * N_CLASS)) + i);
            s.x += v.x; s.y += v.y; s.z += v.z; s.w += v.w;
        }
        out[i * 4 + 0] = s.x * (1.f / N_FOREST);
        out[i * 4 + 1] = s.y * (1.f / N_FOREST);
        out[i * 4 + 2] = s.z * (1.f / N_FOREST);
        out[i * 4 + 3] = s.w * (1.f / N_FOREST);
    }
}

// =====================================================================
extern "C" void kernel_launch(void* const* d_in, const int* in_sizes, int n_in,
                              void* d_out, int out_size) {
    const float* x     = (const float*)d_in[0];
    const float* w1    = (const float*)d_in[1];
    const float* b1    = (const float*)d_in[2];
    const int*   perm  = (const int*)  d_in[3];
    const float* gn1w  = (const float*)d_in[4];
    const float* gn1b  = (const float*)d_in[5];
    const float* c2w   = (const float*)d_in[6];
    const float* c2b   = (const float*)d_in[7];
    const float* gn2w  = (const float*)d_in[8];
    const float* gn2b  = (const float*)d_in[9];
    const float* c3w   = (const float*)d_in[10];
    const float* c3b   = (const float*)d_in[11];
    const int*   swr   = (const int*)  d_in[12];
    const float* E     = (const float*)d_in[13];
    const float* ln1w  = (const float*)d_in[14];
    const float* ln1b  = (const float*)d_in[15];
    const float* fc1w  = (const float*)d_in[16];
    const float* fc1b  = (const float*)d_in[17];
    const float* ln2w  = (const float*)d_in[18];
    const float* ln2b  = (const float*)d_in[19];
    const float* fc2w  = (const float*)d_in[20];
    const float* fc2b  = (const float*)d_in[21];
    float* out = (float*)d_out;

    cudaFuncSetAttribute(k23_forest_mlp, cudaFuncAttributeMaxDynamicSharedMemorySize, K23_SMEM);

    k0_transpose<<<(N_COL * BATCH) / 256, 256>>>(x);
    k_pre<<<(N_RODT * N_HID + 255) / 256, 256>>>(E, fc1w, ln1w, fc2w, ln2w);
    k_pre2<<<1, 128>>>(fc1w, fc1b, ln1b, fc2w, fc2b, ln2b);
    k1_rodt<<<dim3(N_RODT, BATCH / 1024), 256>>>(w1, b1, perm, gn1w, gn1b,
                                                 c2w, c2b, gn2w, gn2b, c3w, c3b);
    k23_forest_mlp<<<dim3(BATCH / 128, N_FOREST), 512, K23_SMEM>>>(swr);
    k4_reduce<<<(BATCH * N_CLASS / 4 + 255) / 256, 256>>>(out);
}